// round 3
// baseline (speedup 1.0000x reference)
#include <cuda_runtime.h>

// PassiveWaveDigitalMixer — fused 9-point periodic stencil + gated flows.
// B=4, C=128, H=W=256, O=16, M=32 (fixed shapes).
// R2: one warp covers a full W row (32 lanes x 8 elems); horizontal halos via
// warp shuffles (periodic wrap inside the warp). s = up+down folding halves
// the live stencil registers and shuffles.

constexpr int B = 4, C = 128, H = 256, W = 256, O = 16, M = 32;
constexpr int HW = H * W;
constexpr float GAIN_CAP = 0.99f;
constexpr float EPS = 1e-4f;

__device__ __forceinline__ float softplus_eps(float p) {
    return fmaxf(p, 0.0f) + log1pf(expf(-fabsf(p))) + EPS;
}

__device__ __forceinline__ float clampg(float v) {
    return fminf(fmaxf(v, 0.0f), GAIN_CAP);
}

__global__ __launch_bounds__(256)
void pwdm_kernel(const float* __restrict__ x,
                 const float* __restrict__ steer,
                 const float* __restrict__ modulation,
                 const float* __restrict__ r_center,
                 const float* __restrict__ r_horizontal,
                 const float* __restrict__ r_vertical,
                 const float* __restrict__ r_diag,
                 const float* __restrict__ gain_h,
                 const float* __restrict__ gain_v,
                 const float* __restrict__ gain_d,
                 const float* __restrict__ steer_w,
                 const float* __restrict__ mod_w,
                 float* __restrict__ out)
{
    __shared__ float s_invh[C], s_invv[C], s_invd[C];
    __shared__ float s_gh[C],   s_gv[C],   s_gd[C];
    __shared__ float s_th[W],   s_tv[W],   s_td[W];

    const int tx  = threadIdx.x;          // 0..31 lane (8 w-elems each)
    const int ty  = threadIdx.y;          // 0..7  channel sub-lane
    const int tid = ty * 32 + tx;
    const int h   = blockIdx.x;
    const int b   = blockIdx.y;

    // --- modulation deltas: every thread computes all 3 (broadcast loads) ---
    float d0 = 0.f, d1 = 0.f, d2 = 0.f;
    #pragma unroll
    for (int m = 0; m < M; m++) {
        float mv = modulation[b * M + m];
        d0 = fmaf(mv, mod_w[0 * M + m], d0);
        d1 = fmaf(mv, mod_w[1 * M + m], d1);
        d2 = fmaf(mv, mod_w[2 * M + m], d2);
    }
    d0 = tanhf(d0); d1 = tanhf(d1); d2 = tanhf(d2);

    // --- per-channel constants ---
    if (tid < C) {
        float spc = softplus_eps(r_center[tid]);
        s_invh[tid] = 1.0f / (spc + softplus_eps(r_horizontal[tid]));
        s_invv[tid] = 1.0f / (spc + softplus_eps(r_vertical[tid]));
        s_invd[tid] = 1.0f / (2.0f * (spc + softplus_eps(r_diag[tid])));
        s_gh[tid] = tanhf(gain_h[tid]) * (1.0f + 0.1f * d0);
        s_gv[tid] = tanhf(gain_v[tid]) * (1.0f + 0.1f * d1);
        s_gd[tid] = tanhf(gain_d[tid]) * (1.0f + 0.1f * d2);
    }

    // --- steer fields: thread tid handles w position = tid (coalesced) ---
    {
        float a0 = 0.f, a1 = 0.f, a2 = 0.f;
        const float* sp = steer + ((size_t)b * O * H + h) * W + tid;
        #pragma unroll
        for (int o = 0; o < O; o++) {
            float v = sp[(size_t)o * HW];
            a0 = fmaf(v, steer_w[0 * O + o], a0);
            a1 = fmaf(v, steer_w[1 * O + o], a1);
            a2 = fmaf(v, steer_w[2 * O + o], a2);
        }
        s_th[tid] = fmaf(0.2f, tanhf(a0), 1.0f);
        s_tv[tid] = fmaf(0.2f, tanhf(a1), 1.0f);
        s_td[tid] = fmaf(0.2f, tanhf(a2), 1.0f);
    }
    __syncthreads();

    // --- hoist this lane's 8 steer multipliers into registers ---
    const int w0 = tx * 8;
    float thr[8], tvr[8], tdr[8];
    #pragma unroll
    for (int i = 0; i < 8; i++) {
        thr[i] = s_th[w0 + i];
        tvr[i] = s_tv[w0 + i];
        tdr[i] = s_td[w0 + i];
    }

    const int hu = (h - 1) & (H - 1);
    const int hd = (h + 1) & (H - 1);
    const size_t base = (size_t)b * C * HW + (size_t)ty * HW;
    const float* pC = x + base + (size_t)h  * W + w0;
    const float* pU = x + base + (size_t)hu * W + w0;
    const float* pD = x + base + (size_t)hd * W + w0;
    float*       po = out + base + (size_t)h * W + w0;
    const size_t cstep = (size_t)8 * HW;

    const unsigned FULL = 0xffffffffu;
    const int laneL = (tx + 31) & 31;
    const int laneR = (tx + 1) & 31;

    #pragma unroll 2
    for (int c = ty; c < C; c += 8) {
        float4 cA = *reinterpret_cast<const float4*>(pC);
        float4 cB = *reinterpret_cast<const float4*>(pC + 4);
        float4 uA = *reinterpret_cast<const float4*>(pU);
        float4 uB = *reinterpret_cast<const float4*>(pU + 4);
        float4 dA = *reinterpret_cast<const float4*>(pD);
        float4 dB = *reinterpret_cast<const float4*>(pD + 4);

        // center + (up+down) sums
        float ce[10], se[10];
        ce[1] = cA.x; ce[2] = cA.y; ce[3] = cA.z; ce[4] = cA.w;
        ce[5] = cB.x; ce[6] = cB.y; ce[7] = cB.z; ce[8] = cB.w;
        se[1] = uA.x + dA.x; se[2] = uA.y + dA.y;
        se[3] = uA.z + dA.z; se[4] = uA.w + dA.w;
        se[5] = uB.x + dB.x; se[6] = uB.y + dB.y;
        se[7] = uB.z + dB.z; se[8] = uB.w + dB.w;

        // horizontal halos: periodic wrap is exactly the warp wrap
        ce[0] = __shfl_sync(FULL, ce[8], laneL);
        ce[9] = __shfl_sync(FULL, ce[1], laneR);
        se[0] = __shfl_sync(FULL, se[8], laneL);
        se[9] = __shfl_sync(FULL, se[1], laneR);

        const float invh = s_invh[c], invv = s_invv[c], invd = s_invd[c];
        const float ghc  = s_gh[c],   gvc  = s_gv[c],   gdc  = s_gd[c];

        float o8[8];
        #pragma unroll
        for (int i = 0; i < 8; i++) {
            float cv = ce[i + 1];
            float fh = (ce[i] + ce[i + 2] - 2.0f * cv) * invh;
            float fv = (se[i + 1]          - 2.0f * cv) * invv;
            float fd = (se[i] + se[i + 2]  - 4.0f * cv) * invd;
            float gh = clampg(ghc * thr[i]);
            float gv = clampg(gvc * tvr[i]);
            float gd = clampg(gdc * tdr[i]);
            o8[i] = fmaf(gh, fh, fmaf(gv, fv, fmaf(gd, fd, cv)));
        }

        *reinterpret_cast<float4*>(po)     = make_float4(o8[0], o8[1], o8[2], o8[3]);
        *reinterpret_cast<float4*>(po + 4) = make_float4(o8[4], o8[5], o8[6], o8[7]);

        pC += cstep; pU += cstep; pD += cstep; po += cstep;
    }
}

extern "C" void kernel_launch(void* const* d_in, const int* in_sizes, int n_in,
                              void* d_out, int out_size)
{
    const float* x            = (const float*)d_in[0];
    const float* steer        = (const float*)d_in[1];
    const float* modulation   = (const float*)d_in[2];
    const float* r_center     = (const float*)d_in[3];
    const float* r_horizontal = (const float*)d_in[4];
    const float* r_vertical   = (const float*)d_in[5];
    const float* r_diag       = (const float*)d_in[6];
    const float* gain_h       = (const float*)d_in[7];
    const float* gain_v       = (const float*)d_in[8];
    const float* gain_d       = (const float*)d_in[9];
    const float* steer_w      = (const float*)d_in[10];
    const float* mod_w        = (const float*)d_in[11];
    float* out = (float*)d_out;

    dim3 block(32, 8, 1);   // one warp per full W row, 8 channel sub-lanes
    dim3 grid(H, B, 1);     // one block per (h, b)
    pwdm_kernel<<<grid, block>>>(x, steer, modulation,
                                 r_center, r_horizontal, r_vertical, r_diag,
                                 gain_h, gain_v, gain_d,
                                 steer_w, mod_w, out);
}

// round 4
// speedup vs baseline: 1.1694x; 1.1694x over previous
#include <cuda_runtime.h>

// PassiveWaveDigitalMixer — fused 9-point periodic stencil + gated flows.
// B=4, C=128, H=W=256, O=16, M=32 (fixed shapes).
// R3: warp covers full W row (32 lanes x 8 elems) AND produces TWO consecutive
// h rows per channel iteration. 4 row-loads serve 2 output rows (middle rows
// reused as vertical neighbors in registers) -> 25% fewer L1 ops, 8-deep LDG
// batch per iteration.

constexpr int B = 4, C = 128, H = 256, W = 256, O = 16, M = 32;
constexpr int HW = H * W;
constexpr float GAIN_CAP = 0.99f;
constexpr float EPS = 1e-4f;

__device__ __forceinline__ float softplus_eps(float p) {
    return fmaxf(p, 0.0f) + log1pf(expf(-fabsf(p))) + EPS;
}

__device__ __forceinline__ float clampg(float v) {
    return fminf(fmaxf(v, 0.0f), GAIN_CAP);
}

__global__ __launch_bounds__(256, 2)
void pwdm_kernel(const float* __restrict__ x,
                 const float* __restrict__ steer,
                 const float* __restrict__ modulation,
                 const float* __restrict__ r_center,
                 const float* __restrict__ r_horizontal,
                 const float* __restrict__ r_vertical,
                 const float* __restrict__ r_diag,
                 const float* __restrict__ gain_h,
                 const float* __restrict__ gain_v,
                 const float* __restrict__ gain_d,
                 const float* __restrict__ steer_w,
                 const float* __restrict__ mod_w,
                 float* __restrict__ out)
{
    __shared__ float s_invh[C], s_invv[C], s_invd[C];
    __shared__ float s_gh[C],   s_gv[C],   s_gd[C];
    // steer multipliers for both rows: [2][W]
    __shared__ float s_th[2][W], s_tv[2][W], s_td[2][W];

    const int tx  = threadIdx.x;          // 0..31 lane (8 w-elems each)
    const int ty  = threadIdx.y;          // 0..7  channel sub-lane
    const int tid = ty * 32 + tx;
    const int h0  = blockIdx.x * 2;       // first of the row pair
    const int h1  = h0 + 1;
    const int b   = blockIdx.y;

    // --- modulation deltas (broadcast loads, every thread) ---
    float d0 = 0.f, d1 = 0.f, d2 = 0.f;
    #pragma unroll
    for (int m = 0; m < M; m++) {
        float mv = modulation[b * M + m];
        d0 = fmaf(mv, mod_w[0 * M + m], d0);
        d1 = fmaf(mv, mod_w[1 * M + m], d1);
        d2 = fmaf(mv, mod_w[2 * M + m], d2);
    }
    d0 = tanhf(d0); d1 = tanhf(d1); d2 = tanhf(d2);

    // --- per-channel constants ---
    if (tid < C) {
        float spc = softplus_eps(r_center[tid]);
        s_invh[tid] = 1.0f / (spc + softplus_eps(r_horizontal[tid]));
        s_invv[tid] = 1.0f / (spc + softplus_eps(r_vertical[tid]));
        s_invd[tid] = 1.0f / (2.0f * (spc + softplus_eps(r_diag[tid])));
        s_gh[tid] = tanhf(gain_h[tid]) * (1.0f + 0.1f * d0);
        s_gv[tid] = tanhf(gain_v[tid]) * (1.0f + 0.1f * d1);
        s_gd[tid] = tanhf(gain_d[tid]) * (1.0f + 0.1f * d2);
    }

    // --- steer fields for both rows; thread tid covers w = tid ---
    #pragma unroll
    for (int r = 0; r < 2; r++) {
        float a0 = 0.f, a1 = 0.f, a2 = 0.f;
        const float* sp = steer + ((size_t)b * O * H + (h0 + r)) * W + tid;
        #pragma unroll
        for (int o = 0; o < O; o++) {
            float v = sp[(size_t)o * HW];
            a0 = fmaf(v, steer_w[0 * O + o], a0);
            a1 = fmaf(v, steer_w[1 * O + o], a1);
            a2 = fmaf(v, steer_w[2 * O + o], a2);
        }
        s_th[r][tid] = fmaf(0.2f, tanhf(a0), 1.0f);
        s_tv[r][tid] = fmaf(0.2f, tanhf(a1), 1.0f);
        s_td[r][tid] = fmaf(0.2f, tanhf(a2), 1.0f);
    }
    __syncthreads();

    // --- hoist this lane's steer multipliers (both rows) ---
    const int w0 = tx * 8;
    float th0[8], tv0[8], td0[8], th1[8], tv1[8], td1[8];
    #pragma unroll
    for (int i = 0; i < 8; i++) {
        th0[i] = s_th[0][w0 + i]; tv0[i] = s_tv[0][w0 + i]; td0[i] = s_td[0][w0 + i];
        th1[i] = s_th[1][w0 + i]; tv1[i] = s_tv[1][w0 + i]; td1[i] = s_td[1][w0 + i];
    }

    const int hm = (h0 - 1) & (H - 1);
    const int hp = (h1 + 1) & (H - 1);
    const size_t base = (size_t)b * C * HW + (size_t)ty * HW;
    const float* pM = x + base + (size_t)hm * W + w0;
    const float* p0 = x + base + (size_t)h0 * W + w0;
    const float* p1 = x + base + (size_t)h1 * W + w0;
    const float* pP = x + base + (size_t)hp * W + w0;
    float*       o0 = out + base + (size_t)h0 * W + w0;
    float*       o1 = out + base + (size_t)h1 * W + w0;
    const size_t cstep = (size_t)8 * HW;

    const unsigned FULL = 0xffffffffu;
    const int laneL = (tx + 31) & 31;
    const int laneR = (tx + 1) & 31;

    for (int c = ty; c < C; c += 8) {
        // front-batch all 8 row loads (max MLP)
        float4 mA = *reinterpret_cast<const float4*>(pM);
        float4 mB = *reinterpret_cast<const float4*>(pM + 4);
        float4 aA = *reinterpret_cast<const float4*>(p0);
        float4 aB = *reinterpret_cast<const float4*>(p0 + 4);
        float4 bA = *reinterpret_cast<const float4*>(p1);
        float4 bB = *reinterpret_cast<const float4*>(p1 + 4);
        float4 pA = *reinterpret_cast<const float4*>(pP);
        float4 pB = *reinterpret_cast<const float4*>(pP + 4);

        const float invh = s_invh[c], invv = s_invv[c], invd = s_invd[c];
        const float ghc  = s_gh[c],   gvc  = s_gv[c],   gdc  = s_gd[c];

        // ---- row h0: center = a, vertical sum = m + b ----
        {
            float ce[10], se[10];
            ce[1] = aA.x; ce[2] = aA.y; ce[3] = aA.z; ce[4] = aA.w;
            ce[5] = aB.x; ce[6] = aB.y; ce[7] = aB.z; ce[8] = aB.w;
            se[1] = mA.x + bA.x; se[2] = mA.y + bA.y;
            se[3] = mA.z + bA.z; se[4] = mA.w + bA.w;
            se[5] = mB.x + bB.x; se[6] = mB.y + bB.y;
            se[7] = mB.z + bB.z; se[8] = mB.w + bB.w;
            ce[0] = __shfl_sync(FULL, ce[8], laneL);
            ce[9] = __shfl_sync(FULL, ce[1], laneR);
            se[0] = __shfl_sync(FULL, se[8], laneL);
            se[9] = __shfl_sync(FULL, se[1], laneR);

            float r8[8];
            #pragma unroll
            for (int i = 0; i < 8; i++) {
                float cv = ce[i + 1];
                float fh = (ce[i] + ce[i + 2] - 2.0f * cv) * invh;
                float fv = (se[i + 1]          - 2.0f * cv) * invv;
                float fd = (se[i] + se[i + 2]  - 4.0f * cv) * invd;
                float gh = clampg(ghc * th0[i]);
                float gv = clampg(gvc * tv0[i]);
                float gd = clampg(gdc * td0[i]);
                r8[i] = fmaf(gh, fh, fmaf(gv, fv, fmaf(gd, fd, cv)));
            }
            *reinterpret_cast<float4*>(o0)     = make_float4(r8[0], r8[1], r8[2], r8[3]);
            *reinterpret_cast<float4*>(o0 + 4) = make_float4(r8[4], r8[5], r8[6], r8[7]);
        }

        // ---- row h1: center = b, vertical sum = a + p ----
        {
            float ce[10], se[10];
            ce[1] = bA.x; ce[2] = bA.y; ce[3] = bA.z; ce[4] = bA.w;
            ce[5] = bB.x; ce[6] = bB.y; ce[7] = bB.z; ce[8] = bB.w;
            se[1] = aA.x + pA.x; se[2] = aA.y + pA.y;
            se[3] = aA.z + pA.z; se[4] = aA.w + pA.w;
            se[5] = aB.x + pB.x; se[6] = aB.y + pB.y;
            se[7] = aB.z + pB.z; se[8] = aB.w + pB.w;
            ce[0] = __shfl_sync(FULL, ce[8], laneL);
            ce[9] = __shfl_sync(FULL, ce[1], laneR);
            se[0] = __shfl_sync(FULL, se[8], laneL);
            se[9] = __shfl_sync(FULL, se[1], laneR);

            float r8[8];
            #pragma unroll
            for (int i = 0; i < 8; i++) {
                float cv = ce[i + 1];
                float fh = (ce[i] + ce[i + 2] - 2.0f * cv) * invh;
                float fv = (se[i + 1]          - 2.0f * cv) * invv;
                float fd = (se[i] + se[i + 2]  - 4.0f * cv) * invd;
                float gh = clampg(ghc * th1[i]);
                float gv = clampg(gvc * tv1[i]);
                float gd = clampg(gdc * td1[i]);
                r8[i] = fmaf(gh, fh, fmaf(gv, fv, fmaf(gd, fd, cv)));
            }
            *reinterpret_cast<float4*>(o1)     = make_float4(r8[0], r8[1], r8[2], r8[3]);
            *reinterpret_cast<float4*>(o1 + 4) = make_float4(r8[4], r8[5], r8[6], r8[7]);
        }

        pM += cstep; p0 += cstep; p1 += cstep; pP += cstep;
        o0 += cstep; o1 += cstep;
    }
}

extern "C" void kernel_launch(void* const* d_in, const int* in_sizes, int n_in,
                              void* d_out, int out_size)
{
    const float* x            = (const float*)d_in[0];
    const float* steer        = (const float*)d_in[1];
    const float* modulation   = (const float*)d_in[2];
    const float* r_center     = (const float*)d_in[3];
    const float* r_horizontal = (const float*)d_in[4];
    const float* r_vertical   = (const float*)d_in[5];
    const float* r_diag       = (const float*)d_in[6];
    const float* gain_h       = (const float*)d_in[7];
    const float* gain_v       = (const float*)d_in[8];
    const float* gain_d       = (const float*)d_in[9];
    const float* steer_w      = (const float*)d_in[10];
    const float* mod_w        = (const float*)d_in[11];
    float* out = (float*)d_out;

    dim3 block(32, 8, 1);       // one warp per full W row-pair, 8 channel lanes
    dim3 grid(H / 2, B, 1);     // one block per (row-pair, b)
    pwdm_kernel<<<grid, block>>>(x, steer, modulation,
                                 r_center, r_horizontal, r_vertical, r_diag,
                                 gain_h, gain_v, gain_d,
                                 steer_w, mod_w, out);
}

// round 5
// speedup vs baseline: 1.2440x; 1.0637x over previous
#include <cuda_runtime.h>
#include <cuda_fp16.h>

// PassiveWaveDigitalMixer — fused 9-point periodic stencil + gated flows.
// B=4, C=128, H=W=256, O=16, M=32 (fixed shapes).
// R4: one warp covers a full W row (32 lanes x 8 elems) and FOUR consecutive
// h rows per channel iteration: 6 row-loads serve 4 output rows (interior rows
// reused as vertical/diag neighbors in registers) -> 0.625 L1 ops/elem.
// Steer-field tanh is held in registers as __half2 (48 regs for 4 rows),
// expanded per use with fmaf(0.2, t, 1.0) — abs err ~2.4e-4 on tanh -> ~5e-5
// on the gain, far below the 1e-3 tolerance.

constexpr int B = 4, C = 128, H = 256, W = 256, O = 16, M = 32;
constexpr int HW = H * W;
constexpr float GAIN_CAP = 0.99f;
constexpr float EPS = 1e-4f;

__device__ __forceinline__ float softplus_eps(float p) {
    return fmaxf(p, 0.0f) + log1pf(expf(-fabsf(p))) + EPS;
}

__device__ __forceinline__ float clampg(float v) {
    return fminf(fmaxf(v, 0.0f), GAIN_CAP);
}

__device__ __forceinline__ float4 add4(float4 a, float4 b) {
    return make_float4(a.x + b.x, a.y + b.y, a.z + b.z, a.w + b.w);
}

__global__ __launch_bounds__(256, 2)
void pwdm_kernel(const float* __restrict__ x,
                 const float* __restrict__ steer,
                 const float* __restrict__ modulation,
                 const float* __restrict__ r_center,
                 const float* __restrict__ r_horizontal,
                 const float* __restrict__ r_vertical,
                 const float* __restrict__ r_diag,
                 const float* __restrict__ gain_h,
                 const float* __restrict__ gain_v,
                 const float* __restrict__ gain_d,
                 const float* __restrict__ steer_w,
                 const float* __restrict__ mod_w,
                 float* __restrict__ out)
{
    __shared__ float s_invh[C], s_invv[C], s_invd[C];
    __shared__ float s_gh[C],   s_gv[C],   s_gd[C];
    __shared__ __half s_t[4][3][W];   // tanh(steer field) per row / direction

    const int tx  = threadIdx.x;          // 0..31 lane (8 w-elems each)
    const int ty  = threadIdx.y;          // 0..7  channel sub-lane
    const int tid = ty * 32 + tx;
    const int h0  = blockIdx.x * 4;       // first of the 4-row group
    const int b   = blockIdx.y;

    // --- modulation deltas (broadcast loads, every thread) ---
    float d0 = 0.f, d1 = 0.f, d2 = 0.f;
    #pragma unroll
    for (int m = 0; m < M; m++) {
        float mv = modulation[b * M + m];
        d0 = fmaf(mv, mod_w[0 * M + m], d0);
        d1 = fmaf(mv, mod_w[1 * M + m], d1);
        d2 = fmaf(mv, mod_w[2 * M + m], d2);
    }
    d0 = tanhf(d0); d1 = tanhf(d1); d2 = tanhf(d2);

    // --- per-channel constants ---
    if (tid < C) {
        float spc = softplus_eps(r_center[tid]);
        s_invh[tid] = 1.0f / (spc + softplus_eps(r_horizontal[tid]));
        s_invv[tid] = 1.0f / (spc + softplus_eps(r_vertical[tid]));
        s_invd[tid] = 1.0f / (2.0f * (spc + softplus_eps(r_diag[tid])));
        s_gh[tid] = tanhf(gain_h[tid]) * (1.0f + 0.1f * d0);
        s_gv[tid] = tanhf(gain_v[tid]) * (1.0f + 0.1f * d1);
        s_gd[tid] = tanhf(gain_d[tid]) * (1.0f + 0.1f * d2);
    }

    // --- steer-field tanh for 4 rows; thread tid covers w = tid ---
    #pragma unroll
    for (int r = 0; r < 4; r++) {
        float a0 = 0.f, a1 = 0.f, a2 = 0.f;
        const float* sp = steer + ((size_t)b * O * H + (h0 + r)) * W + tid;
        #pragma unroll
        for (int o = 0; o < O; o++) {
            float v = sp[(size_t)o * HW];
            a0 = fmaf(v, steer_w[0 * O + o], a0);
            a1 = fmaf(v, steer_w[1 * O + o], a1);
            a2 = fmaf(v, steer_w[2 * O + o], a2);
        }
        s_t[r][0][tid] = __float2half(tanhf(a0));
        s_t[r][1][tid] = __float2half(tanhf(a1));
        s_t[r][2][tid] = __float2half(tanhf(a2));
    }
    __syncthreads();

    // --- hoist this lane's steer tanh values: 4 rows x 3 dirs x 4 half2 ---
    const int w0 = tx * 8;
    __half2 st[4][3][4];
    #pragma unroll
    for (int r = 0; r < 4; r++)
        #pragma unroll
        for (int dir = 0; dir < 3; dir++)
            #pragma unroll
            for (int j = 0; j < 4; j++)
                st[r][dir][j] =
                    *reinterpret_cast<const __half2*>(&s_t[r][dir][w0 + 2 * j]);

    const int hm = (h0 - 1) & (H - 1);
    const int hp = (h0 + 4) & (H - 1);
    const size_t base = (size_t)b * C * HW + (size_t)ty * HW + w0;
    const float* pm = x + base + (size_t)hm * W;   // row h0-1 (wrap)
    const float* p0 = x + base + (size_t)h0 * W;   // rows h0..h0+3 via +W offs
    const float* pp = x + base + (size_t)hp * W;   // row h0+4 (wrap)
    float*       o0 = out + base + (size_t)h0 * W;
    const size_t cstep = (size_t)8 * HW;

    const unsigned FULL = 0xffffffffu;
    const int laneL = (tx + 31) & 31;
    const int laneR = (tx + 1) & 31;

    float invh, invv, invd, ghc, gvc, gdc;

    // process one output row: center pair (cA,cB), vertical-sum pair (sA,sB)
    auto do_row = [&](float4 cA_, float4 cB_, float4 sA_, float4 sB_,
                      __half2 (&stR)[3][4], float* op) {
        float ce[10], se[10];
        ce[1] = cA_.x; ce[2] = cA_.y; ce[3] = cA_.z; ce[4] = cA_.w;
        ce[5] = cB_.x; ce[6] = cB_.y; ce[7] = cB_.z; ce[8] = cB_.w;
        se[1] = sA_.x; se[2] = sA_.y; se[3] = sA_.z; se[4] = sA_.w;
        se[5] = sB_.x; se[6] = sB_.y; se[7] = sB_.z; se[8] = sB_.w;
        ce[0] = __shfl_sync(FULL, ce[8], laneL);
        ce[9] = __shfl_sync(FULL, ce[1], laneR);
        se[0] = __shfl_sync(FULL, se[8], laneL);
        se[9] = __shfl_sync(FULL, se[1], laneR);

        float r8[8];
        #pragma unroll
        for (int j = 0; j < 4; j++) {
            float2 tH = __half22float2(stR[0][j]);
            float2 tV = __half22float2(stR[1][j]);
            float2 tD = __half22float2(stR[2][j]);
            #pragma unroll
            for (int k = 0; k < 2; k++) {
                const int i = 2 * j + k;
                float cv = ce[i + 1];
                float fh = (ce[i] + ce[i + 2] - 2.0f * cv) * invh;
                float fv = (se[i + 1]          - 2.0f * cv) * invv;
                float fd = (se[i] + se[i + 2]  - 4.0f * cv) * invd;
                float th = k ? tH.y : tH.x;
                float tv = k ? tV.y : tV.x;
                float td = k ? tD.y : tD.x;
                float gh = clampg(ghc * fmaf(0.2f, th, 1.0f));
                float gv = clampg(gvc * fmaf(0.2f, tv, 1.0f));
                float gd = clampg(gdc * fmaf(0.2f, td, 1.0f));
                r8[i] = fmaf(gh, fh, fmaf(gv, fv, fmaf(gd, fd, cv)));
            }
        }
        *reinterpret_cast<float4*>(op)     = make_float4(r8[0], r8[1], r8[2], r8[3]);
        *reinterpret_cast<float4*>(op + 4) = make_float4(r8[4], r8[5], r8[6], r8[7]);
    };

    for (int c = ty; c < C; c += 8) {
        // front-batch all 12 row-vector loads (max MLP)
        float4 mA = *reinterpret_cast<const float4*>(pm);
        float4 mB = *reinterpret_cast<const float4*>(pm + 4);
        float4 aA = *reinterpret_cast<const float4*>(p0);
        float4 aB = *reinterpret_cast<const float4*>(p0 + 4);
        float4 bA = *reinterpret_cast<const float4*>(p0 + W);
        float4 bB = *reinterpret_cast<const float4*>(p0 + W + 4);
        float4 cA = *reinterpret_cast<const float4*>(p0 + 2 * W);
        float4 cB = *reinterpret_cast<const float4*>(p0 + 2 * W + 4);
        float4 dA = *reinterpret_cast<const float4*>(p0 + 3 * W);
        float4 dB = *reinterpret_cast<const float4*>(p0 + 3 * W + 4);
        float4 pA = *reinterpret_cast<const float4*>(pp);
        float4 pB = *reinterpret_cast<const float4*>(pp + 4);

        invh = s_invh[c]; invv = s_invv[c]; invd = s_invd[c];
        ghc  = s_gh[c];   gvc  = s_gv[c];   gdc  = s_gd[c];

        // row h0: sum = m + b   (m dead after)
        do_row(aA, aB, add4(mA, bA), add4(mB, bB), st[0], o0);
        // row h1: sum = a + c   (a dead after)
        do_row(bA, bB, add4(aA, cA), add4(aB, cB), st[1], o0 + W);
        // row h2: sum = b + d
        do_row(cA, cB, add4(bA, dA), add4(bB, dB), st[2], o0 + 2 * W);
        // row h3: sum = c + p
        do_row(dA, dB, add4(cA, pA), add4(cB, pB), st[3], o0 + 3 * W);

        pm += cstep; p0 += cstep; pp += cstep; o0 += cstep;
    }
}

extern "C" void kernel_launch(void* const* d_in, const int* in_sizes, int n_in,
                              void* d_out, int out_size)
{
    const float* x            = (const float*)d_in[0];
    const float* steer        = (const float*)d_in[1];
    const float* modulation   = (const float*)d_in[2];
    const float* r_center     = (const float*)d_in[3];
    const float* r_horizontal = (const float*)d_in[4];
    const float* r_vertical   = (const float*)d_in[5];
    const float* r_diag       = (const float*)d_in[6];
    const float* gain_h       = (const float*)d_in[7];
    const float* gain_v       = (const float*)d_in[8];
    const float* gain_d       = (const float*)d_in[9];
    const float* steer_w      = (const float*)d_in[10];
    const float* mod_w        = (const float*)d_in[11];
    float* out = (float*)d_out;

    dim3 block(32, 8, 1);       // one warp per full W row-quad, 8 channel lanes
    dim3 grid(H / 4, B, 1);     // one block per (4-row group, b)
    pwdm_kernel<<<grid, block>>>(x, steer, modulation,
                                 r_center, r_horizontal, r_vertical, r_diag,
                                 gain_h, gain_v, gain_d,
                                 steer_w, mod_w, out);
}

// round 6
// speedup vs baseline: 1.3365x; 1.0744x over previous
#include <cuda_runtime.h>
#include <cuda_fp16.h>

// PassiveWaveDigitalMixer — fused 9-point periodic stencil + gated flows.
// B=4, C=128, H=W=256, O=16, M=32 (fixed shapes).
// R5: R4 structure (warp = full W row x 4 consecutive h rows per channel
// iteration, shuffles for horizontal halos) + packed-half2 gating path:
// steer multipliers pre-expanded to (1+0.2 tanh) in half, per-channel gains
// broadcast as half2, gain = hmin2(hmax2(hmul2(g, m), 0), cap) — ~30% fewer
// issue slots than the fp32 gating path. Flow math stays fp32.

constexpr int B = 4, C = 128, H = 256, W = 256, O = 16, M = 32;
constexpr int HW = H * W;
constexpr float GAIN_CAP = 0.99f;
constexpr float EPS = 1e-4f;

__device__ __forceinline__ float softplus_eps(float p) {
    return fmaxf(p, 0.0f) + log1pf(expf(-fabsf(p))) + EPS;
}

__device__ __forceinline__ float4 add4(float4 a, float4 b) {
    return make_float4(a.x + b.x, a.y + b.y, a.z + b.z, a.w + b.w);
}

__global__ __launch_bounds__(256, 2)
void pwdm_kernel(const float* __restrict__ x,
                 const float* __restrict__ steer,
                 const float* __restrict__ modulation,
                 const float* __restrict__ r_center,
                 const float* __restrict__ r_horizontal,
                 const float* __restrict__ r_vertical,
                 const float* __restrict__ r_diag,
                 const float* __restrict__ gain_h,
                 const float* __restrict__ gain_v,
                 const float* __restrict__ gain_d,
                 const float* __restrict__ steer_w,
                 const float* __restrict__ mod_w,
                 float* __restrict__ out)
{
    __shared__ float s_invh[C], s_invv[C], s_invd[C];
    __shared__ float s_gh[C],   s_gv[C],   s_gd[C];
    __shared__ __half s_t[4][3][W];   // pre-expanded (1 + 0.2*tanh(field))

    const int tx  = threadIdx.x;          // 0..31 lane (8 w-elems each)
    const int ty  = threadIdx.y;          // 0..7  channel sub-lane
    const int tid = ty * 32 + tx;
    const int h0  = blockIdx.x * 4;       // first of the 4-row group
    const int b   = blockIdx.y;

    // --- modulation deltas (broadcast loads, every thread) ---
    float d0 = 0.f, d1 = 0.f, d2 = 0.f;
    #pragma unroll
    for (int m = 0; m < M; m++) {
        float mv = modulation[b * M + m];
        d0 = fmaf(mv, mod_w[0 * M + m], d0);
        d1 = fmaf(mv, mod_w[1 * M + m], d1);
        d2 = fmaf(mv, mod_w[2 * M + m], d2);
    }
    d0 = tanhf(d0); d1 = tanhf(d1); d2 = tanhf(d2);

    // --- per-channel constants ---
    if (tid < C) {
        float spc = softplus_eps(r_center[tid]);
        s_invh[tid] = 1.0f / (spc + softplus_eps(r_horizontal[tid]));
        s_invv[tid] = 1.0f / (spc + softplus_eps(r_vertical[tid]));
        s_invd[tid] = 1.0f / (2.0f * (spc + softplus_eps(r_diag[tid])));
        s_gh[tid] = tanhf(gain_h[tid]) * (1.0f + 0.1f * d0);
        s_gv[tid] = tanhf(gain_v[tid]) * (1.0f + 0.1f * d1);
        s_gd[tid] = tanhf(gain_d[tid]) * (1.0f + 0.1f * d2);
    }

    // --- steer-field multipliers for 4 rows; thread tid covers w = tid ---
    #pragma unroll
    for (int r = 0; r < 4; r++) {
        float a0 = 0.f, a1 = 0.f, a2 = 0.f;
        const float* sp = steer + ((size_t)b * O * H + (h0 + r)) * W + tid;
        #pragma unroll
        for (int o = 0; o < O; o++) {
            float v = sp[(size_t)o * HW];
            a0 = fmaf(v, steer_w[0 * O + o], a0);
            a1 = fmaf(v, steer_w[1 * O + o], a1);
            a2 = fmaf(v, steer_w[2 * O + o], a2);
        }
        s_t[r][0][tid] = __float2half(fmaf(0.2f, tanhf(a0), 1.0f));
        s_t[r][1][tid] = __float2half(fmaf(0.2f, tanhf(a1), 1.0f));
        s_t[r][2][tid] = __float2half(fmaf(0.2f, tanhf(a2), 1.0f));
    }
    __syncthreads();

    // --- hoist this lane's multipliers: 4 rows x 3 dirs x 4 half2 regs ---
    const int w0 = tx * 8;
    __half2 st[4][3][4];
    #pragma unroll
    for (int r = 0; r < 4; r++)
        #pragma unroll
        for (int dir = 0; dir < 3; dir++)
            #pragma unroll
            for (int j = 0; j < 4; j++)
                st[r][dir][j] =
                    *reinterpret_cast<const __half2*>(&s_t[r][dir][w0 + 2 * j]);

    const int hm = (h0 - 1) & (H - 1);
    const int hp = (h0 + 4) & (H - 1);
    const size_t base = (size_t)b * C * HW + (size_t)ty * HW + w0;
    const float* pm = x + base + (size_t)hm * W;
    const float* p0 = x + base + (size_t)h0 * W;
    const float* pp = x + base + (size_t)hp * W;
    float*       o0 = out + base + (size_t)h0 * W;
    const size_t cstep = (size_t)8 * HW;

    const unsigned FULL = 0xffffffffu;
    const int laneL = (tx + 31) & 31;
    const int laneR = (tx + 1) & 31;
    const __half2 zero2 = __float2half2_rn(0.0f);
    const __half2 cap2  = __float2half2_rn(GAIN_CAP);

    float invh, invv, invd;
    __half2 gh2, gv2, gd2;

    // one output row: centers (cA,cB), vertical sums (sA,sB), its multipliers
    auto do_row = [&](float4 cA_, float4 cB_, float4 sA_, float4 sB_,
                      __half2 (&stR)[3][4], float* op) {
        float ce[10], se[10];
        ce[1] = cA_.x; ce[2] = cA_.y; ce[3] = cA_.z; ce[4] = cA_.w;
        ce[5] = cB_.x; ce[6] = cB_.y; ce[7] = cB_.z; ce[8] = cB_.w;
        se[1] = sA_.x; se[2] = sA_.y; se[3] = sA_.z; se[4] = sA_.w;
        se[5] = sB_.x; se[6] = sB_.y; se[7] = sB_.z; se[8] = sB_.w;
        ce[0] = __shfl_sync(FULL, ce[8], laneL);
        ce[9] = __shfl_sync(FULL, ce[1], laneR);
        se[0] = __shfl_sync(FULL, se[8], laneL);
        se[9] = __shfl_sync(FULL, se[1], laneR);

        float r8[8];
        #pragma unroll
        for (int j = 0; j < 4; j++) {
            // packed half2 gating: gain = clamp(g_c * mult, 0, cap)
            __half2 gH = __hmin2(__hmax2(__hmul2(gh2, stR[0][j]), zero2), cap2);
            __half2 gV = __hmin2(__hmax2(__hmul2(gv2, stR[1][j]), zero2), cap2);
            __half2 gD = __hmin2(__hmax2(__hmul2(gd2, stR[2][j]), zero2), cap2);
            float2 ghf = __half22float2(gH);
            float2 gvf = __half22float2(gV);
            float2 gdf = __half22float2(gD);
            #pragma unroll
            for (int k = 0; k < 2; k++) {
                const int i = 2 * j + k;
                float cv = ce[i + 1];
                float fh = (ce[i] + ce[i + 2] - 2.0f * cv) * invh;
                float fv = (se[i + 1]          - 2.0f * cv) * invv;
                float fd = (se[i] + se[i + 2]  - 4.0f * cv) * invd;
                float gh = k ? ghf.y : ghf.x;
                float gv = k ? gvf.y : gvf.x;
                float gd = k ? gdf.y : gdf.x;
                r8[i] = fmaf(gh, fh, fmaf(gv, fv, fmaf(gd, fd, cv)));
            }
        }
        *reinterpret_cast<float4*>(op)     = make_float4(r8[0], r8[1], r8[2], r8[3]);
        *reinterpret_cast<float4*>(op + 4) = make_float4(r8[4], r8[5], r8[6], r8[7]);
    };

    for (int c = ty; c < C; c += 8) {
        // front-batch all 12 row-vector loads (max MLP)
        float4 mA = *reinterpret_cast<const float4*>(pm);
        float4 mB = *reinterpret_cast<const float4*>(pm + 4);
        float4 aA = *reinterpret_cast<const float4*>(p0);
        float4 aB = *reinterpret_cast<const float4*>(p0 + 4);
        float4 bA = *reinterpret_cast<const float4*>(p0 + W);
        float4 bB = *reinterpret_cast<const float4*>(p0 + W + 4);
        float4 cA = *reinterpret_cast<const float4*>(p0 + 2 * W);
        float4 cB = *reinterpret_cast<const float4*>(p0 + 2 * W + 4);
        float4 dA = *reinterpret_cast<const float4*>(p0 + 3 * W);
        float4 dB = *reinterpret_cast<const float4*>(p0 + 3 * W + 4);
        float4 pA = *reinterpret_cast<const float4*>(pp);
        float4 pB = *reinterpret_cast<const float4*>(pp + 4);

        invh = s_invh[c]; invv = s_invv[c]; invd = s_invd[c];
        gh2 = __float2half2_rn(s_gh[c]);
        gv2 = __float2half2_rn(s_gv[c]);
        gd2 = __float2half2_rn(s_gd[c]);

        // row h0: vsum = m + b
        do_row(aA, aB, add4(mA, bA), add4(mB, bB), st[0], o0);
        // row h1: vsum = a + c
        do_row(bA, bB, add4(aA, cA), add4(aB, cB), st[1], o0 + W);
        // row h2: vsum = b + d
        do_row(cA, cB, add4(bA, dA), add4(bB, dB), st[2], o0 + 2 * W);
        // row h3: vsum = c + p
        do_row(dA, dB, add4(cA, pA), add4(cB, pB), st[3], o0 + 3 * W);

        pm += cstep; p0 += cstep; pp += cstep; o0 += cstep;
    }
}

extern "C" void kernel_launch(void* const* d_in, const int* in_sizes, int n_in,
                              void* d_out, int out_size)
{
    const float* x            = (const float*)d_in[0];
    const float* steer        = (const float*)d_in[1];
    const float* modulation   = (const float*)d_in[2];
    const float* r_center     = (const float*)d_in[3];
    const float* r_horizontal = (const float*)d_in[4];
    const float* r_vertical   = (const float*)d_in[5];
    const float* r_diag       = (const float*)d_in[6];
    const float* gain_h       = (const float*)d_in[7];
    const float* gain_v       = (const float*)d_in[8];
    const float* gain_d       = (const float*)d_in[9];
    const float* steer_w      = (const float*)d_in[10];
    const float* mod_w        = (const float*)d_in[11];
    float* out = (float*)d_out;

    dim3 block(32, 8, 1);       // one warp per full W row-quad, 8 channel lanes
    dim3 grid(H / 4, B, 1);     // one block per (4-row group, b)
    pwdm_kernel<<<grid, block>>>(x, steer, modulation,
                                 r_center, r_horizontal, r_vertical, r_diag,
                                 gain_h, gain_v, gain_d,
                                 steer_w, mod_w, out);
}